// round 16
// baseline (speedup 1.0000x reference)
#include <cuda_runtime.h>

#define TT 35
#define CC 4
#define CIN 7
#define HH 64
#define BN_EPS 1e-5
#define SVPB 128        // voxels per stats-phase block (thread-half-voxel)
#define NSMAX 160       // max stats blocks (N <= 20480)
#define NCAP 20480      // per-voxel mean scratch capacity

// raw partials: 0..9 = P (upper-tri sum v v^T), 10..13 = S, 14..34 = corr
__device__ float g_part[35][NSMAX];
__device__ unsigned g_ticket;     // stats contributors; reset each replay
__device__ unsigned g_ticket2;    // exit ticket; reset each replay
__device__ unsigned g_flag;       // fold-done flag; reset each replay
__device__ float4 g_mean[NCAP];   // per-voxel mean of ch0..2
__device__ float g_WpT[CIN * HH]; // BN-folded weights, transposed [k][j]
__device__ float g_bp[HH];

__device__ __forceinline__ void accum_v(float4 v, float* accP,
                                        float& s0, float& s1, float& s2, float& s3,
                                        float& cnt) {
    s0 += v.x; s1 += v.y; s2 += v.z; s3 += v.w;
    float rs = v.x + v.y + v.z + v.w;
    cnt += (rs != 0.f) ? 1.f : 0.f;
    accP[0] = fmaf(v.x, v.x, accP[0]);
    accP[1] = fmaf(v.y, v.x, accP[1]);
    accP[2] = fmaf(v.y, v.y, accP[2]);
    accP[3] = fmaf(v.z, v.x, accP[3]);
    accP[4] = fmaf(v.z, v.y, accP[4]);
    accP[5] = fmaf(v.z, v.z, accP[5]);
    accP[6] = fmaf(v.w, v.x, accP[6]);
    accP[7] = fmaf(v.w, v.y, accP[7]);
    accP[8] = fmaf(v.w, v.z, accP[8]);
    accP[9] = fmaf(v.w, v.w, accP[9]);
}

__device__ __forceinline__ void fma4(float4& v, const float4 w, float a) {
    v.x = fmaf(w.x, a, v.x);
    v.y = fmaf(w.y, a, v.y);
    v.z = fmaf(w.z, a, v.z);
    v.w = fmaf(w.w, a, v.w);
}

// Single fused kernel. Blocks 0..nStats-1 (all wave-1 resident at 3
// blocks/SM) compute BN moment partials; last contributor folds BN into the
// linear layer and releases g_flag. All blocks prefetch their own 4-voxel
// tile first, wait on the flag, then run the proven 256-thread compute/store
// phase. Exit ticket resets flags for graph replay.
__global__ __launch_bounds__(256, 3) void fused_kernel(
        const float* __restrict__ vox, float* __restrict__ out, int N,
        const float* __restrict__ Wm, const float* __restrict__ bvec,
        const float* __restrict__ gamma, const float* __restrict__ beta,
        int nStats) {
    __shared__ float4 srow[4 * TT];
    __shared__ float  swpT[CIN][HH];
    __shared__ float  sbp[HH];
    __shared__ float4 spmax[4][4][16];
    __shared__ float4 smaxf[4][16];
    __shared__ float  swacc[8][35];
    __shared__ float  spart[35][7];
    __shared__ double sraw[35];
    __shared__ double sstat[35];
    __shared__ bool   s_last;

    const unsigned FULL = 0xffffffffu;
    int tid = threadIdx.x;
    int base = blockIdx.x * 4;

    // prefetch this block's voxel tile early (weight-independent)
    {
        int nv4 = min(4, N - base) * TT;
        if (tid < nv4)
            srow[tid] = ((const float4*)vox)[(size_t)base * TT + tid];
    }

    // ---------------- stats phase (blocks 0..nStats-1 only) ----------------
    if (blockIdx.x < nStats) {
        int lane = tid & 31;
        int w = tid >> 5;
        int v0 = tid >> 1;             // voxel within this stats block
        int sub = tid & 1;             // half: rows 0-17 / 18-34
        int n = blockIdx.x * SVPB + v0;
        bool act = (n < N);

        float accP[10];
#pragma unroll
        for (int i = 0; i < 10; i++) accP[i] = 0.f;
        float s0 = 0.f, s1 = 0.f, s2 = 0.f, s3 = 0.f, cnt = 0.f;

        if (act) {
            const float4* vp = (const float4*)vox + (size_t)n * TT;
            int r0 = sub * 18;
            int nRows = 18 - sub;      // 18 for sub0, 17 for sub1
            float4 buf[9];
            // chunk 0: rows 0..8 (always valid)
#pragma unroll
            for (int i = 0; i < 9; i++) buf[i] = vp[r0 + i];
#pragma unroll
            for (int i = 0; i < 9; i++) accum_v(buf[i], accP, s0, s1, s2, s3, cnt);
            // chunk 1: rows 9..17 (guard last row for sub1)
#pragma unroll
            for (int i = 9; i < 18; i++)
                if (i < nRows) buf[i - 9] = vp[r0 + i];
#pragma unroll
            for (int i = 9; i < 18; i++)
                if (i < nRows) accum_v(buf[i - 9], accP, s0, s1, s2, s3, cnt);
        }

        float p0 = s0, p1 = s1, p2 = s2, p3 = s3;   // pre-merge copies for S

        // merge the thread pair: one shfl level
        s0  += __shfl_xor_sync(FULL, s0, 1);
        s1  += __shfl_xor_sync(FULL, s1, 1);
        s2  += __shfl_xor_sync(FULL, s2, 1);
        s3  += __shfl_xor_sync(FULL, s3, 1);
        cnt += __shfl_xor_sync(FULL, cnt, 1);

        float corr[21];
#pragma unroll
        for (int i = 0; i < 21; i++) corr[i] = 0.f;

        if (act && sub == 0) {
            float rc = 1.f / cnt;
            float m0 = s0 * rc, m1 = s1 * rc, m2 = s2 * rc;
            if (n < NCAP) g_mean[n] = make_float4(m0, m1, m2, 0.f);
            corr[0]  = -m0 * s0; corr[1]  = -m0 * s1; corr[2]  = -m0 * s2; corr[3]  = -m0 * s3;
            corr[4]  = -m1 * s0; corr[5]  = -m1 * s1; corr[6]  = -m1 * s2; corr[7]  = -m1 * s3;
            corr[8]  = -m2 * s0; corr[9]  = -m2 * s1; corr[10] = -m2 * s2; corr[11] = -m2 * s3;
            corr[12] = 35.f * m0 * m0 - 2.f * m0 * s0;
            corr[13] = 35.f * m1 * m0 - m1 * s0 - m0 * s1;
            corr[14] = 35.f * m1 * m1 - 2.f * m1 * s1;
            corr[15] = 35.f * m2 * m0 - m2 * s0 - m0 * s2;
            corr[16] = 35.f * m2 * m1 - m2 * s1 - m1 * s2;
            corr[17] = 35.f * m2 * m2 - 2.f * m2 * s2;
            corr[18] = -35.f * m0; corr[19] = -35.f * m1; corr[20] = -35.f * m2;
        }

        // one uniform 35-value warp reduce
        float st[35];
#pragma unroll
        for (int i = 0; i < 10; i++) st[i] = accP[i];
        st[10] = p0; st[11] = p1; st[12] = p2; st[13] = p3;
#pragma unroll
        for (int i = 0; i < 21; i++) st[14 + i] = corr[i];
#pragma unroll
        for (int off = 16; off; off >>= 1) {
#pragma unroll
            for (int i = 0; i < 35; i++) st[i] += __shfl_xor_sync(FULL, st[i], off);
        }
        if (lane == 0) {
#pragma unroll
            for (int i = 0; i < 35; i++) swacc[w][i] = st[i];
        }
        __syncthreads();
        if (tid < 35) {
            float s = 0.f;
#pragma unroll
            for (int ww = 0; ww < 8; ww++) s += swacc[ww][tid];
            g_part[tid][blockIdx.x] = s;
        }
        __threadfence();

        if (tid == 0) {
            unsigned t = atomicAdd(&g_ticket, 1u);
            s_last = (t == (unsigned)nStats - 1u);
        }
        __syncthreads();

        if (s_last) {
            // ---- in-block fold (runs once, by the last stats contributor) ----
            __threadfence();
            if (tid < 245) {               // 35 stats x 7 sub-summers
                int s = tid / 7, k = tid % 7;
                float acc = 0.f;
                for (int bb = k; bb < nStats; bb += 7) acc += __ldcg(&g_part[s][bb]);
                spart[s][k] = acc;
            }
            __syncthreads();
            if (tid < 35) {
                double s = 0.0;
#pragma unroll
                for (int k = 0; k < 7; k++) s += (double)spart[tid][k];
                sraw[tid] = s;
            }
            __syncthreads();
            if (tid < 35) {
                static const int pureTab[35] = {0,1,2,3,4,5,6,7,8,9,
                                                0,1,3,6, 0, 1,2,4,7, 1,2, 3,4,5,8, 3,4,5,
                                                10,11,12,13, 10,11,12};
                static const int corrTab[35] = {-1,-1,-1,-1,-1,-1,-1,-1,-1,-1,
                                                0,1,2,3, 12, 4,5,6,7, 13,14, 8,9,10,11, 15,16,17,
                                                -1,-1,-1,-1, 18,19,20};
                double v = sraw[pureTab[tid]];
                int c = corrTab[tid];
                if (c >= 0) v += sraw[14 + c];
                sstat[tid] = v;            // assembled M(0..27), S1(28..34)
            }
            __syncthreads();
            if (tid < HH) {
                int j = tid;
                double wv[7];
#pragma unroll
                for (int k = 0; k < 7; k++) wv[k] = (double)Wm[j * CIN + k];
                double bj = (double)bvec[j];
                double dotWS = 0.0;
#pragma unroll
                for (int k = 0; k < 7; k++) dotWS += wv[k] * sstat[28 + k];
                double quad = 0.0;
                int idx = 0;
#pragma unroll
                for (int k = 0; k < 7; k++) {
#pragma unroll
                    for (int l = 0; l <= k; l++) {
                        double term = wv[k] * wv[l] * sstat[idx];
                        quad += (l == k) ? term : 2.0 * term;
                        idx++;
                    }
                }
                double Nt = (double)N * (double)TT;
                double sumx  = dotWS + Nt * bj;
                double sumxx = quad + 2.0 * bj * dotWS + Nt * bj * bj;
                double mu  = sumx / Nt;
                double var = sumxx / Nt - mu * mu;
                double inv = 1.0 / sqrt(var + (double)BN_EPS);
                double a = (double)gamma[j] * inv;
#pragma unroll
                for (int k = 0; k < 7; k++) g_WpT[k * HH + j] = (float)(a * wv[k]);
                g_bp[j] = (float)((double)beta[j] + a * (bj - mu));
            }
            __syncthreads();
            if (tid == 0) {
                __threadfence();                 // release fold writes
                atomicExch(&g_flag, 1u);
            }
        }
    }

    // ---------------- wait for fold, then reset bookkeeping ----------------
    if (tid == 0) {
        while (atomicAdd(&g_flag, 0u) == 0u) __nanosleep(64);
        __threadfence();                         // acquire
        unsigned t2 = atomicAdd(&g_ticket2, 1u);
        if (t2 == gridDim.x - 1u) {              // all blocks passed the wait
            g_ticket = 0; g_ticket2 = 0; g_flag = 0;
        }
    }
    __syncthreads();

    // stage folded weights (valid only after the flag)
    if (tid < HH) {
#pragma unroll
        for (int k = 0; k < CIN; k++) swpT[k][tid] = g_WpT[k * HH + tid];
        sbp[tid] = g_bp[tid];
    }
    __syncthreads();

    // ---------------- main compute/store phase (proven 56us path) ----------
    int sub = tid >> 6;
    int j = tid & 63;
    int g = j & 15, tq = j >> 4;
    int n = base + sub;
    bool active = (n < N);

    float4 pmax = make_float4(0.f, 0.f, 0.f, 0.f);
    float* ob = out + (size_t)n * (TT * 2 * HH) + g * 4;

    if (active) {
        float4 w0 = *(const float4*)&swpT[0][g * 4];
        float4 w1 = *(const float4*)&swpT[1][g * 4];
        float4 w2 = *(const float4*)&swpT[2][g * 4];
        float4 w3 = *(const float4*)&swpT[3][g * 4];
        float4 w4 = *(const float4*)&swpT[4][g * 4];
        float4 w5 = *(const float4*)&swpT[5][g * 4];
        float4 w6 = *(const float4*)&swpT[6][g * 4];
        float4 bias = *(const float4*)&sbp[g * 4];

        float mx, my, mz;
        if (n < NCAP) {
            float4 m = g_mean[n];
            mx = m.x; my = m.y; mz = m.z;
        } else {
            float sx = 0.f, sy = 0.f, sz = 0.f, cnt2 = 0.f;
            for (int t = 0; t < TT; t++) {
                float4 r = srow[sub * TT + t];
                sx += r.x; sy += r.y; sz += r.z;
                if (r.x + r.y + r.z + r.w != 0.f) cnt2 += 1.f;
            }
            float inv = 1.f / cnt2;
            mx = sx * inv; my = sy * inv; mz = sz * inv;
        }

        const float4* sr = &srow[sub * TT];
#pragma unroll
        for (int i = 0; i < 9; i++) {
            int t = tq + i * 4;
            if (t < TT) {
                float4 r = sr[t];
                float4 v = bias;
                fma4(v, w0, r.x);
                fma4(v, w1, r.y);
                fma4(v, w2, r.z);
                fma4(v, w3, r.w);
                fma4(v, w4, r.x - mx);
                fma4(v, w5, r.y - my);
                fma4(v, w6, r.z - mz);
                v.x = fmaxf(v.x, 0.f); v.y = fmaxf(v.y, 0.f);
                v.z = fmaxf(v.z, 0.f); v.w = fmaxf(v.w, 0.f);
                pmax.x = fmaxf(pmax.x, v.x); pmax.y = fmaxf(pmax.y, v.y);
                pmax.z = fmaxf(pmax.z, v.z); pmax.w = fmaxf(pmax.w, v.w);
                __stcs((float4*)(ob + t * (2 * HH)), v);
            }
        }
    }
    spmax[sub][tq][g] = pmax;
    __syncthreads();

    if (tid < 64) {
        int s2 = tid >> 4, g2 = tid & 15;
        float4 a = spmax[s2][0][g2], b2 = spmax[s2][1][g2];
        float4 c = spmax[s2][2][g2], d = spmax[s2][3][g2];
        float4 m;
        m.x = fmaxf(fmaxf(a.x, b2.x), fmaxf(c.x, d.x));
        m.y = fmaxf(fmaxf(a.y, b2.y), fmaxf(c.y, d.y));
        m.z = fmaxf(fmaxf(a.z, b2.z), fmaxf(c.z, d.z));
        m.w = fmaxf(fmaxf(a.w, b2.w), fmaxf(c.w, d.w));
        smaxf[s2][g2] = m;
    }
    __syncthreads();

    if (active) {
        float4 mv = smaxf[sub][g];
        float* obm = ob + HH;
#pragma unroll
        for (int i = 0; i < 9; i++) {
            int t = tq + i * 4;
            if (t < TT) __stcs((float4*)(obm + t * (2 * HH)), mv);
        }
    }
}

extern "C" void kernel_launch(void* const* d_in, const int* in_sizes, int n_in,
                              void* d_out, int out_size) {
    const float* vox   = (const float*)d_in[0];
    const float* Wm    = (const float*)d_in[1];
    const float* b     = (const float*)d_in[2];
    const float* gamma = (const float*)d_in[3];
    const float* beta  = (const float*)d_in[4];
    float* out = (float*)d_out;

    int N = in_sizes[0] / (TT * CC);
    int nStats = (N + SVPB - 1) / SVPB;
    if (nStats > NSMAX) nStats = NSMAX;   // N <= 20480 for this problem

    int grid = (N + 3) / 4;               // >= nStats always (128 > 4)
    fused_kernel<<<grid, 256>>>(vox, out, N, Wm, b, gamma, beta, nStats);
}